// round 11
// baseline (speedup 1.0000x reference)
#include <cuda_runtime.h>
#include <math.h>
#include <float.h>

#define B 4
#define T 8
#define NF 8192
#define C 384
#define H 12
#define TOPK 32
#define D 32
#define HT (H*T)        /* 96 */
#define ROWS (T+NF)     /* 8200 */
#define NH (NF/2)       /* 4096 per stage-1 half */
#define SCALE 0.17677669529663687f

typedef unsigned long long ull;
typedef unsigned int uint;

// ---------------- scratch (static device globals; no runtime alloc) ----------
__device__ float g_q[B*T*C];                      // 48KB
__device__ float g_at[B*T*C];                     // 48KB
__device__ float g_qk[B*HT*C];
__device__ float g_attn[(size_t)B*HT*NF];         // ~12.6MB
__device__ ull   g_cand[B*HT][2][TOPK];           // stage-1 sorted candidates

// ---------------- helpers -----------------------------------------------------
__device__ __forceinline__ void red_add_v4(float* p, float4 v) {
    asm volatile("red.global.add.v4.f32 [%0], {%1, %2, %3, %4};"
                 :: "l"(p), "f"(v.x), "f"(v.y), "f"(v.z), "f"(v.w) : "memory");
}
__device__ __forceinline__ void mma_tf32(float* d,
                                         uint a0, uint a1, uint a2, uint a3,
                                         uint b0, uint b1) {
    asm("mma.sync.aligned.m16n8k8.row.col.f32.tf32.tf32.f32 "
        "{%0,%1,%2,%3}, {%4,%5,%6,%7}, {%8,%9}, {%0,%1,%2,%3};"
        : "+f"(d[0]), "+f"(d[1]), "+f"(d[2]), "+f"(d[3])
        : "r"(a0), "r"(a1), "r"(a2), "r"(a3), "r"(b0), "r"(b1));
}
__device__ __forceinline__ uint sptr(const void* p) {
    return (uint)__cvta_generic_to_shared(p);
}
__device__ __forceinline__ void cp16(uint dst, const float* src) {
    asm volatile("cp.async.cg.shared.global [%0], [%1], 16;" :: "r"(dst), "l"(src));
}
#define HIMASK 0xffffe000u

__device__ __forceinline__ unsigned enc_key(unsigned b) {
    return (b & 0x80000000u) ? ~b : (b | 0x80000000u);
}
__device__ __forceinline__ float dec_key(unsigned u) {
    unsigned b = (u & 0x80000000u) ? (u ^ 0x80000000u) : ~u;
    return __uint_as_float(b);
}

// ---------------- kernel: zero output + scratch accumulators ------------------
__global__ void zero_all_kernel(float4* __restrict__ out, int n4) {
    int total = n4 + 2*(B*T*C/4);          // out + g_q + g_at (as float4)
    float4 z = make_float4(0.f, 0.f, 0.f, 0.f);
    for (int i = blockIdx.x * blockDim.x + threadIdx.x; i < total;
         i += gridDim.x * blockDim.x) {
        if (i < n4) out[i] = z;
        else {
            int j = i - n4;
            if (j < B*T*C/4) ((float4*)g_q)[j] = z;
            else             ((float4*)g_at)[j - B*T*C/4] = z;
        }
    }
}

// ---------------- kernel: q projection, c-split with atomic reduction ---------
__global__ __launch_bounds__(384) void q_kernel(const float* __restrict__ x,
                                                const float* __restrict__ qs_w) {
    int cs = blockIdx.x, t = blockIdx.y;
    int tid = threadIdx.x;
    __shared__ float xs[4][48];
    if (tid < 192) {
        int b = tid / 48, c = tid % 48;
        xs[b][c] = x[((size_t)b*ROWS + t)*C + cs*48 + c];
    }
    __syncthreads();
    float a0 = 0.f, a1 = 0.f, a2 = 0.f, a3 = 0.f;
    const float* w = qs_w + (size_t)t*C*C + (size_t)cs*48*C + tid;
    #pragma unroll 4
    for (int c = 0; c < 48; c++) {
        float wv = w[(size_t)c*C];
        a0 += xs[0][c]*wv; a1 += xs[1][c]*wv;
        a2 += xs[2][c]*wv; a3 += xs[3][c]*wv;
    }
    atomicAdd(&g_q[(0*T + t)*C + tid], a0);
    atomicAdd(&g_q[(1*T + t)*C + tid], a1);
    atomicAdd(&g_q[(2*T + t)*C + tid], a2);
    atomicAdd(&g_q[(3*T + t)*C + tid], a3);
}

// ---------------- kernel: qk fold ---------------------------------------------
#define QPAD 392
#define QK_SMEM_BYTES ((32*QPAD + 4*QPAD)*4)
__global__ __launch_bounds__(384) void qk_kernel(const float* __restrict__ kv_w) {
    extern __shared__ float qsm[];
    float* qs  = qsm;                      // [32][QPAD]
    float* kvs = qsm + 32*QPAD;            // [4][QPAD]

    int c0 = blockIdx.x * 4;
    int tid = threadIdx.x;
    int h = tid >> 5, t = (tid >> 2) & 7, cl = tid & 3;

    #pragma unroll
    for (int r = 0; r < 32; r++) qs[r*QPAD + tid] = g_q[r*C + tid];
    #pragma unroll
    for (int r = 0; r < 4; r++)
        kvs[r*QPAD + tid] = kv_w[(size_t)(c0 + r)*(2*C) + tid];
    __syncthreads();

    const float* krow = &kvs[cl*QPAD + h*D];
    #pragma unroll
    for (int b = 0; b < 4; b++) {
        const float* qrow = &qs[(b*8 + t)*QPAD + h*D];
        float s = 0.f;
        #pragma unroll
        for (int d = 0; d < D; d++) s += qrow[d] * krow[d];
        g_qk[(((size_t)b*H + h)*T + t)*C + c0 + cl] = s * SCALE;
    }
}

// ---------------- kernel: attn GEMM (FROZEN: 49.4us, tensor 54.5%) -----------
#define KSTRIDE 36
#define A_FL (96*KSTRIDE)
#define B_FL (128*KSTRIDE)
#define GEMM_SMEM_BYTES ((2*A_FL + 2*B_FL)*4)

__global__ __launch_bounds__(256, 2) void attn_gemm_kernel(const float* __restrict__ x) {
    extern __shared__ __align__(16) float smem_f[];
    float* sA0 = smem_f;
    float* sA1 = smem_f + A_FL;
    float* sB0 = smem_f + 2*A_FL;
    float* sB1 = smem_f + 2*A_FL + B_FL;

    int b  = blockIdx.y;
    int n0 = blockIdx.x * 128;
    int tid = threadIdx.x;
    int wid = tid >> 5, lane = tid & 31;
    int g = lane >> 2, tig = lane & 3;
    int wm = wid & 1, wn = wid >> 1;

    const float* qk   = g_qk + (size_t)b*HT*C;
    const float* feat = x + ((size_t)b*ROWS + T)*C;

    int ar[3], ak[3], br[4], bk[4];
    #pragma unroll
    for (int j = 0; j < 3; j++) { int idx = tid + j*256; ar[j] = idx >> 3; ak[j] = (idx & 7)*4; }
    #pragma unroll
    for (int j = 0; j < 4; j++) { int idx = tid + j*256; br[j] = idx >> 3; bk[j] = (idx & 7)*4; }

    float acc[3][4][4];
    #pragma unroll
    for (int i = 0; i < 3; i++)
        #pragma unroll
        for (int j = 0; j < 4; j++)
            #pragma unroll
            for (int r = 0; r < 4; r++) acc[i][j][r] = 0.f;

    {
        #pragma unroll
        for (int j = 0; j < 3; j++)
            cp16(sptr(&sA0[ar[j]*KSTRIDE + ak[j]]), qk + (size_t)ar[j]*C + ak[j]);
        #pragma unroll
        for (int j = 0; j < 4; j++)
            cp16(sptr(&sB0[br[j]*KSTRIDE + bk[j]]), feat + (size_t)(n0 + br[j])*C + bk[j]);
        asm volatile("cp.async.commit_group;");
    }

    #pragma unroll 1
    for (int t = 0; t < 12; t++) {
        if (t < 11) {
            int c1 = (t + 1) * 32;
            float* dA = ((t + 1) & 1) ? sA1 : sA0;
            float* dB = ((t + 1) & 1) ? sB1 : sB0;
            #pragma unroll
            for (int j = 0; j < 3; j++)
                cp16(sptr(&dA[ar[j]*KSTRIDE + ak[j]]), qk + (size_t)ar[j]*C + c1 + ak[j]);
            #pragma unroll
            for (int j = 0; j < 4; j++)
                cp16(sptr(&dB[br[j]*KSTRIDE + bk[j]]), feat + (size_t)(n0 + br[j])*C + c1 + bk[j]);
            asm volatile("cp.async.commit_group;");
            asm volatile("cp.async.wait_group 1;");
        } else {
            asm volatile("cp.async.wait_group 0;");
        }
        __syncthreads();

        const float* cA = (t & 1) ? sA1 : sA0;
        const float* cB = (t & 1) ? sB1 : sB0;

        #pragma unroll
        for (int k8 = 0; k8 < 4; k8++) {
            int kc = k8*8 + tig;
            uint bh[4][2], bl[4][2];
            #pragma unroll
            for (int nt = 0; nt < 4; nt++) {
                int n = wn*32 + nt*8 + g;
                float b0 = cB[n*KSTRIDE + kc];
                float b1 = cB[n*KSTRIDE + kc + 4];
                uint u0 = __float_as_uint(b0) & HIMASK;
                uint u1 = __float_as_uint(b1) & HIMASK;
                bh[nt][0] = u0; bh[nt][1] = u1;
                bl[nt][0] = __float_as_uint(b0 - __uint_as_float(u0));
                bl[nt][1] = __float_as_uint(b1 - __uint_as_float(u1));
            }
            #pragma unroll
            for (int mt = 0; mt < 3; mt++) {
                int m0 = wm*48 + mt*16;
                float a0 = cA[(m0 + g    )*KSTRIDE + kc];
                float a1 = cA[(m0 + g + 8)*KSTRIDE + kc];
                float a2 = cA[(m0 + g    )*KSTRIDE + kc + 4];
                float a3 = cA[(m0 + g + 8)*KSTRIDE + kc + 4];
                uint ah0 = __float_as_uint(a0) & HIMASK;
                uint ah1 = __float_as_uint(a1) & HIMASK;
                uint ah2 = __float_as_uint(a2) & HIMASK;
                uint ah3 = __float_as_uint(a3) & HIMASK;
                uint al0 = __float_as_uint(a0 - __uint_as_float(ah0));
                uint al1 = __float_as_uint(a1 - __uint_as_float(ah1));
                uint al2 = __float_as_uint(a2 - __uint_as_float(ah2));
                uint al3 = __float_as_uint(a3 - __uint_as_float(ah3));
                #pragma unroll
                for (int nt = 0; nt < 4; nt++) {
                    float* d = acc[mt][nt];
                    mma_tf32(d, ah0, ah1, ah2, ah3, bh[nt][0], bh[nt][1]);
                    mma_tf32(d, ah0, ah1, ah2, ah3, bl[nt][0], bl[nt][1]);
                    mma_tf32(d, al0, al1, al2, al3, bh[nt][0], bh[nt][1]);
                }
            }
        }
        __syncthreads();
    }

    float* outp = g_attn + (size_t)b*HT*NF;
    #pragma unroll
    for (int mt = 0; mt < 3; mt++) {
        int m0 = wm*48 + mt*16;
        #pragma unroll
        for (int nt = 0; nt < 4; nt++) {
            int nc = n0 + wn*32 + nt*8 + 2*tig;
            *(float2*)&outp[(size_t)(m0 + g    )*NF + nc] =
                make_float2(acc[mt][nt][0], acc[mt][nt][1]);
            *(float2*)&outp[(size_t)(m0 + g + 8)*NF + nc] =
                make_float2(acc[mt][nt][2], acc[mt][nt][3]);
        }
    }
}

// ---------------- top-k stage 1: 11-bit histogram + compaction ----------------
__global__ __launch_bounds__(256) void topk_stage1_kernel() {
    int blk  = blockIdx.x;
    int row  = blk >> 1;
    int half = blk & 1;
    int base = half * NH;
    int tid = threadIdx.x;
    int lane = tid & 31, wp = tid >> 5;
    __shared__ unsigned keys[NH];          // 16KB
    __shared__ unsigned hist[2048];        // 8KB (low 128 reused for refine)
    __shared__ int      cidx[NH];          // 16KB (compacted bucket indices)
    __shared__ unsigned wsuf[8];
    __shared__ unsigned sh_pref, sh_need;
    __shared__ int cntG, cntM;
    __shared__ unsigned candK[TOPK];
    __shared__ int candI[TOPK];
    __shared__ int ri[256];

    #pragma unroll
    for (int j = 0; j < 8; j++) hist[tid + j*256] = 0;
    if (tid == 0) { cntG = 0; cntM = 0; }
    __syncthreads();

    // load + 11-bit histogram fused
    const uint4* src = (const uint4*)(g_attn + (size_t)row*NF + base);
    for (int i = tid; i < NH/4; i += 256) {
        uint4 u = src[i];
        unsigned k0 = enc_key(u.x), k1 = enc_key(u.y);
        unsigned k2 = enc_key(u.z), k3 = enc_key(u.w);
        keys[4*i+0] = k0; keys[4*i+1] = k1;
        keys[4*i+2] = k2; keys[4*i+3] = k3;
        atomicAdd(&hist[k0 >> 21], 1u);
        atomicAdd(&hist[k1 >> 21], 1u);
        atomicAdd(&hist[k2 >> 21], 1u);
        atomicAdd(&hist[k3 >> 21], 1u);
    }
    __syncthreads();

    // suffix-sum over 2048 bins: thread owns bins [8t, 8t+8)
    {
        unsigned l[8];
        l[7] = hist[tid*8 + 7];
        #pragma unroll
        for (int j = 6; j >= 0; j--) l[j] = l[j+1] + hist[tid*8 + j];
        unsigned total = l[0];
        unsigned inc = total;
        #pragma unroll
        for (int s = 1; s < 32; s <<= 1) {
            unsigned tv = __shfl_down_sync(0xffffffffu, inc, s);
            if (lane + s < 32) inc += tv;
        }
        if (lane == 0) wsuf[wp] = inc;
        __syncthreads();
        if (tid < 8) {
            unsigned tv = wsuf[tid];
            #pragma unroll
            for (int s = 1; s < 8; s <<= 1) {
                unsigned t2 = __shfl_down_sync(0xffu, tv, s);
                if (tid + s < 8) tv += t2;
            }
            wsuf[tid] = tv;
        }
        __syncthreads();
        unsigned higher = inc - total + (wp < 7 ? wsuf[wp + 1] : 0u);
        #pragma unroll
        for (int j = 0; j < 8; j++) {
            unsigned incl = higher + l[j];
            unsigned excl = higher + (j < 7 ? l[j+1] : 0u);
            if (incl >= TOPK && excl < TOPK) {
                sh_pref = (unsigned)(tid*8 + j) << 21;
                sh_need = TOPK - excl;
            }
        }
        __syncthreads();
    }
    unsigned b11pref = sh_pref;            // bucket<<21

    // collect definite winners (> bucket) + compact bucket members
    for (int i = tid; i < NH; i += 256) {
        unsigned k = keys[i];
        unsigned kp = k & 0xFFE00000u;
        if (kp > b11pref) {
            int p = atomicAdd(&cntG, 1); candK[p] = k; candI[p] = base + i;
        } else if (kp == b11pref) {
            int p = atomicAdd(&cntM, 1); cidx[p] = i;
        }
    }
    __syncthreads();
    int M = cntM;

    // refine remaining 21 bits over compacted list: 3 x 7-bit passes (128 bins)
    #pragma unroll
    for (int pass = 0; pass < 3; pass++) {
        int shift = 14 - 7*pass;
        if (tid < 128) hist[tid] = 0;
        __syncthreads();
        unsigned pref  = sh_pref;
        unsigned pmask = 0xFFFFFFFFu << (shift + 7);
        for (int j = tid; j < M; j += 256) {
            unsigned k = keys[cidx[j]];
            if ((k & pmask) == pref) atomicAdd(&hist[(k >> shift) & 127], 1u);
        }
        __syncthreads();
        unsigned v = (tid < 128) ? hist[tid] : 0u;
        unsigned inc = v;
        #pragma unroll
        for (int s = 1; s < 32; s <<= 1) {
            unsigned tv = __shfl_down_sync(0xffffffffu, inc, s);
            if (lane + s < 32) inc += tv;
        }
        if (lane == 0) wsuf[wp] = inc;
        __syncthreads();
        if (tid < 4) {
            unsigned tv = wsuf[tid];
            #pragma unroll
            for (int s = 1; s < 4; s <<= 1) {
                unsigned t2 = __shfl_down_sync(0xFu, tv, s);
                if (tid + s < 4) tv += t2;
            }
            wsuf[tid] = tv;
        }
        __syncthreads();
        if (tid < 128) {
            unsigned incl = inc + (wp < 3 ? wsuf[wp + 1] : 0u);
            unsigned excl = incl - v;
            unsigned need = sh_need;
            if (incl >= need && excl < need) {
                sh_pref = pref | ((unsigned)tid << shift);
                sh_need = need - excl;
            }
        }
        __syncthreads();
    }
    unsigned V = sh_pref;                  // exact 32nd-largest key
    int E = (int)sh_need;

    // strictly-greater within bucket
    for (int j = tid; j < M; j += 256) {
        unsigned k = keys[cidx[j]];
        if (k > V) { int p = atomicAdd(&cntG, 1); candK[p] = k; candI[p] = base + cidx[j]; }
    }
    __syncthreads();
    int G = cntG;

    // ties: E smallest indices with key == V (scan compacted list only)
    int last = -1;
    for (int e = 0; e < E; e++) {
        int best = NH;
        for (int j = tid; j < M; j += 256) {
            int i = cidx[j];
            if (keys[i] == V && i > last && i < best) best = i;
        }
        ri[tid] = best;
        __syncthreads();
        for (int s = 128; s > 0; s >>= 1) {
            if (tid < s) ri[tid] = min(ri[tid], ri[tid + s]);
            __syncthreads();
        }
        int widx = ri[0];
        if (tid == 0) { candK[G + e] = V; candI[G + e] = base + widx; }
        last = widx;
        __syncthreads();
    }

    // rank-sort 32 candidates: value desc, index asc; write sorted packed
    if (tid < 32) {
        unsigned k = candK[tid];
        int ix = candI[tid];
        ull ck = ((ull)k << 32) | (ull)(0xFFFFFFFFu - (unsigned)ix);
        int rank = 0;
        #pragma unroll
        for (int j = 0; j < 32; j++) {
            ull o = __shfl_sync(0xffffffffu, ck, j);
            rank += (o > ck);
        }
        g_cand[row][half][rank] = ck;
    }
}

// ---------------- kernel: merge + softmax + gather + at-proj + scatter --------
__global__ __launch_bounds__(384) void gather_scatter_kernel(const float* __restrict__ x,
                                                             const float* __restrict__ kv_w,
                                                             const float* __restrict__ experts_w,
                                                             float* __restrict__ out) {
    int t = blockIdx.x, h = blockIdx.y, b = blockIdx.z;
    int tid = threadIdx.x;                 // 384
    __shared__ float wsh[TOPK];
    __shared__ int   ish[TOPK];
    __shared__ float fsh[TOPK][D];
    __shared__ float fbs[C];
    __shared__ __align__(16) float sc[4][C];

    int row = (b*H + h)*T + t;
    // warp 0: merge the two sorted halves + softmax (replaces topk_merge kernel)
    if (tid < 32) {
        ull a = g_cand[row][0][tid];
        ull bq = g_cand[row][1][31 - tid];
        ull cc = a > bq ? a : bq;
        #pragma unroll
        for (int st = 16; st > 0; st >>= 1) {
            ull o = __shfl_xor_sync(0xffffffffu, cc, st);
            bool up = (tid & st) == 0;
            cc = up ? (cc > o ? cc : o) : (cc < o ? cc : o);
        }
        float val = dec_key((unsigned)(cc >> 32));
        int   idx = (int)(0xFFFFFFFFu - (unsigned)(cc & 0xFFFFFFFFu));
        float m = __shfl_sync(0xffffffffu, val, 0);
        float e = expf(val - m);
        float sum = e;
        #pragma unroll
        for (int o = 16; o > 0; o >>= 1) sum += __shfl_xor_sync(0xffffffffu, sum, o);
        wsh[tid] = e / sum;
        ish[tid] = idx;
    }
    __syncthreads();

    const float* feat = x + ((size_t)b*ROWS + T)*C;
    int c = tid;
    int hD = h*D;
    bool mine = (c >= hD) && (c < hD + D);
    int d = c - hD;
    float a = 0.f;
    #pragma unroll
    for (int k = 0; k < TOPK; k++) {
        float v  = feat[(size_t)ish[k]*C + c];
        float wv = wsh[k] * v;
        a += wv;
        if (mine) fsh[k][d] = wv;
    }
    fbs[c] = a;
    __syncthreads();

    // at-projection partials
    {
        int dd = tid & 31, cs = tid >> 5;  // cs 0..11
        float part = 0.f;
        const float* kvv = kv_w + C + hD + dd;
        #pragma unroll 4
        for (int c2 = 0; c2 < 32; c2++) {
            int cc2 = cs*32 + c2;
            part += fbs[cc2] * kvv[(size_t)cc2*(2*C)];
        }
        atomicAdd(&g_at[((size_t)b*T + t)*C + hD + dd], part);
    }

    // sparse scatter
    int o = tid;
    float ecol[D];
    const float* ew = experts_w + ((size_t)t*C + hD)*C + o;
    #pragma unroll
    for (int d2 = 0; d2 < D; d2++) ecol[d2] = ew[(size_t)d2*C];

    float* outb = out + ((size_t)b*ROWS + T)*C;
    int kq = tid / (C/4);
    int o4 = tid % (C/4);
    #pragma unroll 1
    for (int gI = 0; gI < TOPK/4; gI++) {
        #pragma unroll
        for (int j = 0; j < 4; j++) {
            int k = gI*4 + j;
            float s = 0.f;
            #pragma unroll
            for (int d2 = 0; d2 < D; d2++) s += fsh[k][d2] * ecol[d2];
            sc[j][o] = s;
        }
        __syncthreads();
        float4 v = *(const float4*)&sc[kq][4*o4];
        red_add_v4(&outb[(size_t)ish[gI*4 + kq]*C + 4*o4], v);
        __syncthreads();
    }
}

// ---------------- kernel: token_out = at @ experts_w, c-split -----------------
__global__ __launch_bounds__(384) void token_final_kernel(const float* __restrict__ experts_w,
                                                          float* __restrict__ out) {
    int cs = blockIdx.x, t = blockIdx.y;
    int tid = threadIdx.x;
    __shared__ float ats[4][48];
    if (tid < 192) {
        int b = tid / 48, c = tid % 48;
        ats[b][c] = g_at[((size_t)b*T + t)*C + cs*48 + c];
    }
    __syncthreads();
    float a0 = 0.f, a1 = 0.f, a2 = 0.f, a3 = 0.f;
    const float* w = experts_w + (size_t)t*C*C + (size_t)cs*48*C + tid;
    #pragma unroll 4
    for (int c = 0; c < 48; c++) {
        float wv = w[(size_t)c*C];
        a0 += ats[0][c]*wv; a1 += ats[1][c]*wv;
        a2 += ats[2][c]*wv; a3 += ats[3][c]*wv;
    }
    atomicAdd(&out[((size_t)0*ROWS + t)*C + tid], a0);
    atomicAdd(&out[((size_t)1*ROWS + t)*C + tid], a1);
    atomicAdd(&out[((size_t)2*ROWS + t)*C + tid], a2);
    atomicAdd(&out[((size_t)3*ROWS + t)*C + tid], a3);
}

// ---------------- launcher ----------------------------------------------------
extern "C" void kernel_launch(void* const* d_in, const int* in_sizes, int n_in,
                              void* d_out, int out_size) {
    const float* x = nullptr; const float* qs_w = nullptr;
    const float* kv_w = nullptr; const float* experts_w = nullptr;
    for (int i = 0; i < n_in; i++) {
        if (in_sizes[i] == B*ROWS*C)      x = (const float*)d_in[i];
        else if (in_sizes[i] == C*2*C)    kv_w = (const float*)d_in[i];
        else if (in_sizes[i] == T*C*C) {
            if (!qs_w) qs_w = (const float*)d_in[i];
            else       experts_w = (const float*)d_in[i];
        }
    }
    float* out = (float*)d_out;

    cudaFuncSetAttribute(attn_gemm_kernel,
                         cudaFuncAttributeMaxDynamicSharedMemorySize,
                         (int)GEMM_SMEM_BYTES);
    cudaFuncSetAttribute(qk_kernel,
                         cudaFuncAttributeMaxDynamicSharedMemorySize,
                         (int)QK_SMEM_BYTES);

    // launch order puts the NEW topk_stage1 at captured index 3
    q_kernel<<<dim3(8, T), 384>>>(x, qs_w);                              // 0
    qk_kernel<<<96, 384, QK_SMEM_BYTES>>>(kv_w);                         // 1
    attn_gemm_kernel<<<dim3(NF/128, B), 256, GEMM_SMEM_BYTES>>>(x);      // 2
    topk_stage1_kernel<<<B*HT*2, 256>>>();                               // 3
    zero_all_kernel<<<1024, 256>>>((float4*)d_out, out_size / 4);        // 4
    gather_scatter_kernel<<<dim3(T, H, B), 384>>>(x, kv_w, experts_w, out); // 5
    token_final_kernel<<<dim3(8, T), 384>>>(experts_w, out);             // 6
}

// round 13
// speedup vs baseline: 1.2248x; 1.2248x over previous
#include <cuda_runtime.h>
#include <math.h>
#include <float.h>

#define B 4
#define T 8
#define NF 8192
#define C 384
#define H 12
#define TOPK 32
#define D 32
#define HT (H*T)        /* 96 */
#define ROWS (T+NF)     /* 8200 */
#define NH (NF/2)       /* 4096 per stage-1 half */
#define SCALE 0.17677669529663687f

typedef unsigned long long ull;
typedef unsigned int uint;

// ---------------- scratch (static device globals; no runtime alloc) ----------
__device__ float g_q[B*T*C];
__device__ float g_at[B*T*C];
__device__ float g_qk[B*HT*C];
__device__ float g_attn[(size_t)B*HT*NF];         // ~12.6MB
__device__ ull   g_cand[B*HT][2][TOPK];           // stage-1 sorted candidates

// ---------------- helpers -----------------------------------------------------
__device__ __forceinline__ void red_add_v4(float* p, float4 v) {
    asm volatile("red.global.add.v4.f32 [%0], {%1, %2, %3, %4};"
                 :: "l"(p), "f"(v.x), "f"(v.y), "f"(v.z), "f"(v.w) : "memory");
}
__device__ __forceinline__ void mma_bf16(float* d,
                                         uint a0, uint a1, uint a2, uint a3,
                                         uint b0, uint b1) {
    asm("mma.sync.aligned.m16n8k16.row.col.f32.bf16.bf16.f32 "
        "{%0,%1,%2,%3}, {%4,%5,%6,%7}, {%8,%9}, {%0,%1,%2,%3};"
        : "+f"(d[0]), "+f"(d[1]), "+f"(d[2]), "+f"(d[3])
        : "r"(a0), "r"(a1), "r"(a2), "r"(a3), "r"(b0), "r"(b1));
}
__device__ __forceinline__ uint prmt_hi(uint lo, uint hi) {
    uint r; asm("prmt.b32 %0, %1, %2, 0x7632;" : "=r"(r) : "r"(lo), "r"(hi));
    return r;
}
__device__ __forceinline__ uint cvt_bf16x2(float hi, float lo) {
    uint r; asm("cvt.rn.satfinite.bf16x2.f32 %0, %1, %2;" : "=r"(r) : "f"(hi), "f"(lo));
    return r;
}
__device__ __forceinline__ unsigned enc_key(unsigned b) {
    return (b & 0x80000000u) ? ~b : (b | 0x80000000u);
}
__device__ __forceinline__ float dec_key(unsigned u) {
    unsigned b = (u & 0x80000000u) ? (u ^ 0x80000000u) : ~u;
    return __uint_as_float(b);
}

// ---------------- kernel: zero output + scratch accumulators ------------------
__global__ void zero_all_kernel(float4* __restrict__ out, int n4) {
    int total = n4 + 2*(B*T*C/4);
    float4 z = make_float4(0.f, 0.f, 0.f, 0.f);
    for (int i = blockIdx.x * blockDim.x + threadIdx.x; i < total;
         i += gridDim.x * blockDim.x) {
        if (i < n4) out[i] = z;
        else {
            int j = i - n4;
            if (j < B*T*C/4) ((float4*)g_q)[j] = z;
            else             ((float4*)g_at)[j - B*T*C/4] = z;
        }
    }
}

// ---------------- kernel: q projection, c-split with atomic reduction ---------
__global__ __launch_bounds__(384) void q_kernel(const float* __restrict__ x,
                                                const float* __restrict__ qs_w) {
    int cs = blockIdx.x, t = blockIdx.y;
    int tid = threadIdx.x;
    __shared__ float xs[4][48];
    if (tid < 192) {
        int b = tid / 48, c = tid % 48;
        xs[b][c] = x[((size_t)b*ROWS + t)*C + cs*48 + c];
    }
    __syncthreads();
    float a0 = 0.f, a1 = 0.f, a2 = 0.f, a3 = 0.f;
    const float* w = qs_w + (size_t)t*C*C + (size_t)cs*48*C + tid;
    #pragma unroll 4
    for (int c = 0; c < 48; c++) {
        float wv = w[(size_t)c*C];
        a0 += xs[0][c]*wv; a1 += xs[1][c]*wv;
        a2 += xs[2][c]*wv; a3 += xs[3][c]*wv;
    }
    atomicAdd(&g_q[(0*T + t)*C + tid], a0);
    atomicAdd(&g_q[(1*T + t)*C + tid], a1);
    atomicAdd(&g_q[(2*T + t)*C + tid], a2);
    atomicAdd(&g_q[(3*T + t)*C + tid], a3);
}

// ---------------- kernel: qk fold ---------------------------------------------
#define QPAD 392
#define QK_SMEM_BYTES ((32*QPAD + 4*QPAD)*4)
__global__ __launch_bounds__(384) void qk_kernel(const float* __restrict__ kv_w) {
    extern __shared__ float qsm[];
    float* qs  = qsm;                      // [32][QPAD]
    float* kvs = qsm + 32*QPAD;            // [4][QPAD]

    int c0 = blockIdx.x * 4;
    int tid = threadIdx.x;
    int h = tid >> 5, t = (tid >> 2) & 7, cl = tid & 3;

    #pragma unroll
    for (int r = 0; r < 32; r++) qs[r*QPAD + tid] = g_q[r*C + tid];
    #pragma unroll
    for (int r = 0; r < 4; r++)
        kvs[r*QPAD + tid] = kv_w[(size_t)(c0 + r)*(2*C) + tid];
    __syncthreads();

    const float* krow = &kvs[cl*QPAD + h*D];
    #pragma unroll
    for (int b = 0; b < 4; b++) {
        const float* qrow = &qs[(b*8 + t)*QPAD + h*D];
        float s = 0.f;
        #pragma unroll
        for (int d = 0; d < D; d++) s += qrow[d] * krow[d];
        g_qk[(((size_t)b*H + h)*T + t)*C + c0 + cl] = s * SCALE;
    }
}

// ---------------- kernel: attn GEMM, 3xBF16 split, pre-split smem -------------
// Block 96x128, 256 thr, 8 warps (2m x 4n), warp tile 48x32, K-chunk 32.
// smem holds pre-split bf16x2 words: Ah/Al [96][20w], Bh/Bl [128][20w].
// Word j of a row holds k = {2j, 2j+1}. Fragment reads are conflict-free.
#define WPR 20
#define AH_OFF 0
#define AL_OFF (96*WPR)
#define BH_OFF (2*96*WPR)
#define BL_OFF (2*96*WPR + 128*WPR)
#define BUFW   (2*96*WPR + 2*128*WPR)     /* 8960 words */
#define GEMM_SMEM_BYTES (2*BUFW*4)        /* 71680 B */

// FIXED: explicit hi/lo base pointers (the R12 bug was a hardcoded 96*WPR
// hi->lo offset reused for the B tile whose lo region is 128*WPR away).
__device__ __forceinline__ void split_store(uint* hi, uint* lo,
                                            int row, int kq, float4 v) {
    uint bx = __float_as_uint(v.x), by = __float_as_uint(v.y);
    uint bz = __float_as_uint(v.z), bw = __float_as_uint(v.w);
    float lx = v.x - __uint_as_float(bx & 0xFFFF0000u);
    float ly = v.y - __uint_as_float(by & 0xFFFF0000u);
    float lz = v.z - __uint_as_float(bz & 0xFFFF0000u);
    float lw = v.w - __uint_as_float(bw & 0xFFFF0000u);
    uint h0 = prmt_hi(bx, by);
    uint h1 = prmt_hi(bz, bw);
    uint l0 = cvt_bf16x2(ly, lx);
    uint l1 = cvt_bf16x2(lw, lz);
    *(uint2*)&hi[row*WPR + 2*kq] = make_uint2(h0, h1);
    *(uint2*)&lo[row*WPR + 2*kq] = make_uint2(l0, l1);
}

__global__ __launch_bounds__(256, 2) void attn_gemm_kernel(const float* __restrict__ x) {
    extern __shared__ __align__(16) uint smem_u[];

    int b  = blockIdx.y;
    int n0 = blockIdx.x * 128;
    int tid = threadIdx.x;
    int wid = tid >> 5, lane = tid & 31;
    int g = lane >> 2, tig = lane & 3;
    int wm = wid & 1, wn = wid >> 1;       // 2x4 warp grid

    const float* qk   = g_qk + (size_t)b*HT*C;
    const float* feat = x + ((size_t)b*ROWS + T)*C;

    int ar[3], ak[3], br[4], bk[4];
    #pragma unroll
    for (int j = 0; j < 3; j++) { int idx = tid + j*256; ar[j] = idx >> 3; ak[j] = idx & 7; }
    #pragma unroll
    for (int j = 0; j < 4; j++) { int idx = tid + j*256; br[j] = idx >> 3; bk[j] = idx & 7; }

    float acc[3][4][4];
    #pragma unroll
    for (int i = 0; i < 3; i++)
        #pragma unroll
        for (int j = 0; j < 4; j++)
            #pragma unroll
            for (int r = 0; r < 4; r++) acc[i][j][r] = 0.f;

    float4 pa[3], pb[4];
    // load chunk 0
    #pragma unroll
    for (int j = 0; j < 3; j++) pa[j] = *(const float4*)&qk[(size_t)ar[j]*C + ak[j]*4];
    #pragma unroll
    for (int j = 0; j < 4; j++) pb[j] = *(const float4*)&feat[(size_t)(n0 + br[j])*C + bk[j]*4];
    // split+store chunk 0 into buffer 0
    {
        uint* buf = smem_u;
        #pragma unroll
        for (int j = 0; j < 3; j++)
            split_store(buf + AH_OFF, buf + AL_OFF, ar[j], ak[j], pa[j]);
        #pragma unroll
        for (int j = 0; j < 4; j++)
            split_store(buf + BH_OFF, buf + BL_OFF, br[j], bk[j], pb[j]);
    }
    __syncthreads();

    #pragma unroll 1
    for (int t = 0; t < 12; t++) {
        if (t < 11) {                      // prefetch chunk t+1 into registers
            int c1 = (t + 1) * 32;
            #pragma unroll
            for (int j = 0; j < 3; j++)
                pa[j] = *(const float4*)&qk[(size_t)ar[j]*C + c1 + ak[j]*4];
            #pragma unroll
            for (int j = 0; j < 4; j++)
                pb[j] = *(const float4*)&feat[(size_t)(n0 + br[j])*C + c1 + bk[j]*4];
        }

        const uint* buf = smem_u + (t & 1)*BUFW;
        #pragma unroll
        for (int h16 = 0; h16 < 2; h16++) {
            int wo = h16*8;
            uint bh[4][2], bl[4][2];
            #pragma unroll
            for (int nt = 0; nt < 4; nt++) {
                int n = wn*32 + nt*8 + g;
                bh[nt][0] = buf[BH_OFF + n*WPR + wo + tig];
                bh[nt][1] = buf[BH_OFF + n*WPR + wo + tig + 4];
                bl[nt][0] = buf[BL_OFF + n*WPR + wo + tig];
                bl[nt][1] = buf[BL_OFF + n*WPR + wo + tig + 4];
            }
            #pragma unroll
            for (int mt = 0; mt < 3; mt++) {
                int r0 = (wm*48 + mt*16 + g)*WPR + wo;
                int r1 = r0 + 8*WPR;
                uint ah0 = buf[AH_OFF + r0 + tig];
                uint ah1 = buf[AH_OFF + r1 + tig];
                uint ah2 = buf[AH_OFF + r0 + tig + 4];
                uint ah3 = buf[AH_OFF + r1 + tig + 4];
                uint al0 = buf[AL_OFF + r0 + tig];
                uint al1 = buf[AL_OFF + r1 + tig];
                uint al2 = buf[AL_OFF + r0 + tig + 4];
                uint al3 = buf[AL_OFF + r1 + tig + 4];
                #pragma unroll
                for (int nt = 0; nt < 4; nt++) {
                    float* d = acc[mt][nt];
                    mma_bf16(d, ah0, ah1, ah2, ah3, bh[nt][0], bh[nt][1]);
                    mma_bf16(d, ah0, ah1, ah2, ah3, bl[nt][0], bl[nt][1]);
                    mma_bf16(d, al0, al1, al2, al3, bh[nt][0], bh[nt][1]);
                }
            }
        }

        if (t < 11) {                      // split+store chunk t+1
            uint* dbuf = smem_u + ((t + 1) & 1)*BUFW;
            #pragma unroll
            for (int j = 0; j < 3; j++)
                split_store(dbuf + AH_OFF, dbuf + AL_OFF, ar[j], ak[j], pa[j]);
            #pragma unroll
            for (int j = 0; j < 4; j++)
                split_store(dbuf + BH_OFF, dbuf + BL_OFF, br[j], bk[j], pb[j]);
            __syncthreads();
        }
    }

    float* outp = g_attn + (size_t)b*HT*NF;
    #pragma unroll
    for (int mt = 0; mt < 3; mt++) {
        int m0 = wm*48 + mt*16;
        #pragma unroll
        for (int nt = 0; nt < 4; nt++) {
            int nc = n0 + wn*32 + nt*8 + 2*tig;
            *(float2*)&outp[(size_t)(m0 + g    )*NF + nc] =
                make_float2(acc[mt][nt][0], acc[mt][nt][1]);
            *(float2*)&outp[(size_t)(m0 + g + 8)*NF + nc] =
                make_float2(acc[mt][nt][2], acc[mt][nt][3]);
        }
    }
}

// ---------------- top-k stage 1 (measured-15.7us R10 version) -----------------
__global__ __launch_bounds__(256) void topk_stage1_kernel() {
    int blk  = blockIdx.x;
    int row  = blk >> 1;
    int half = blk & 1;
    int base = half * NH;
    int tid = threadIdx.x;
    int lane = tid & 31, wp = tid >> 5;
    __shared__ unsigned keys[NH];
    __shared__ unsigned hist[256];
    __shared__ unsigned wsuf[8];
    __shared__ unsigned sh_need, sh_prefix;
    __shared__ int cntG;
    __shared__ unsigned candK[TOPK];
    __shared__ int candI[TOPK];
    __shared__ int ri[256];

    hist[tid] = 0;
    if (tid == 0) { sh_need = TOPK; sh_prefix = 0; cntG = 0; }
    __syncthreads();

    const uint4* src = (const uint4*)(g_attn + (size_t)row*NF + base);
    for (int i = tid; i < NH/4; i += 256) {
        uint4 u = src[i];
        unsigned k0 = enc_key(u.x), k1 = enc_key(u.y);
        unsigned k2 = enc_key(u.z), k3 = enc_key(u.w);
        keys[4*i+0] = k0; keys[4*i+1] = k1;
        keys[4*i+2] = k2; keys[4*i+3] = k3;
        atomicAdd(&hist[k0 >> 24], 1u);
        atomicAdd(&hist[k1 >> 24], 1u);
        atomicAdd(&hist[k2 >> 24], 1u);
        atomicAdd(&hist[k3 >> 24], 1u);
    }
    __syncthreads();

    #pragma unroll
    for (int pass = 0; pass < 4; pass++) {
        int shift = 24 - 8*pass;
        if (pass > 0) {
            hist[tid] = 0;
            __syncthreads();
            unsigned pref  = sh_prefix;
            unsigned pmask = 0xFFFFFFFFu << (shift + 8);
            for (int i = tid; i < NH; i += 256) {
                unsigned k = keys[i];
                if ((k & pmask) == pref) atomicAdd(&hist[(k >> shift) & 255], 1u);
            }
            __syncthreads();
        }

        unsigned v = hist[tid];
        unsigned inc = v;
        #pragma unroll
        for (int s = 1; s < 32; s <<= 1) {
            unsigned tv = __shfl_down_sync(0xffffffffu, inc, s);
            if (lane + s < 32) inc += tv;
        }
        if (lane == 0) wsuf[wp] = inc;
        __syncthreads();
        if (tid < 8) {
            unsigned tv = wsuf[tid];
            #pragma unroll
            for (int s = 1; s < 8; s <<= 1) {
                unsigned t2 = __shfl_down_sync(0xffu, tv, s);
                if (tid + s < 8) tv += t2;
            }
            wsuf[tid] = tv;
        }
        __syncthreads();
        unsigned incl = inc + (wp < 7 ? wsuf[wp + 1] : 0u);
        unsigned need = sh_need;
        unsigned excl = incl - v;
        if (incl >= need && excl < need) {
            sh_prefix = sh_prefix | ((unsigned)tid << shift);
            sh_need   = need - excl;
        }
        __syncthreads();
    }
    unsigned V = sh_prefix;
    int E = (int)sh_need;

    for (int i = tid; i < NH; i += 256) {
        unsigned k = keys[i];
        if (k > V) { int p = atomicAdd(&cntG, 1); candK[p] = k; candI[p] = base + i; }
    }
    __syncthreads();
    int G = cntG;

    int last = -1;
    for (int e = 0; e < E; e++) {
        int best = NH;
        for (int i = tid; i < NH; i += 256)
            if (keys[i] == V && i > last && i < best) best = i;
        ri[tid] = best;
        __syncthreads();
        for (int s = 128; s > 0; s >>= 1) {
            if (tid < s) ri[tid] = min(ri[tid], ri[tid + s]);
            __syncthreads();
        }
        int widx = ri[0];
        if (tid == 0) { candK[G + e] = V; candI[G + e] = base + widx; }
        last = widx;
        __syncthreads();
    }

    if (tid < 32) {
        unsigned k = candK[tid];
        int ix = candI[tid];
        ull ck = ((ull)k << 32) | (ull)(0xFFFFFFFFu - (unsigned)ix);
        int rank = 0;
        #pragma unroll
        for (int j = 0; j < 32; j++) {
            ull o = __shfl_sync(0xffffffffu, ck, j);
            rank += (o > ck);
        }
        g_cand[row][half][rank] = ck;
    }
}

// ---------------- kernel: merge + softmax + gather + at-proj + scatter --------
__global__ __launch_bounds__(384) void gather_scatter_kernel(const float* __restrict__ x,
                                                             const float* __restrict__ kv_w,
                                                             const float* __restrict__ experts_w,
                                                             float* __restrict__ out) {
    int t = blockIdx.x, h = blockIdx.y, b = blockIdx.z;
    int tid = threadIdx.x;                 // 384
    __shared__ float wsh[TOPK];
    __shared__ int   ish[TOPK];
    __shared__ float fsh[TOPK][D];
    __shared__ float fbs[C];
    __shared__ __align__(16) float sc[4][C];

    int row = (b*H + h)*T + t;
    if (tid < 32) {
        ull a = g_cand[row][0][tid];
        ull bq = g_cand[row][1][31 - tid];
        ull cc = a > bq ? a : bq;
        #pragma unroll
        for (int st = 16; st > 0; st >>= 1) {
            ull o = __shfl_xor_sync(0xffffffffu, cc, st);
            bool up = (tid & st) == 0;
            cc = up ? (cc > o ? cc : o) : (cc < o ? cc : o);
        }
        float val = dec_key((unsigned)(cc >> 32));
        int   idx = (int)(0xFFFFFFFFu - (unsigned)(cc & 0xFFFFFFFFu));
        float m = __shfl_sync(0xffffffffu, val, 0);
        float e = expf(val - m);
        float sum = e;
        #pragma unroll
        for (int o = 16; o > 0; o >>= 1) sum += __shfl_xor_sync(0xffffffffu, sum, o);
        wsh[tid] = e / sum;
        ish[tid] = idx;
    }
    __syncthreads();

    const float* feat = x + ((size_t)b*ROWS + T)*C;
    int c = tid;
    int hD = h*D;
    bool mine = (c >= hD) && (c < hD + D);
    int d = c - hD;
    float a = 0.f;
    #pragma unroll
    for (int k = 0; k < TOPK; k++) {
        float v  = feat[(size_t)ish[k]*C + c];
        float wv = wsh[k] * v;
        a += wv;
        if (mine) fsh[k][d] = wv;
    }
    fbs[c] = a;
    __syncthreads();

    {
        int dd = tid & 31, cs = tid >> 5;
        float part = 0.f;
        const float* kvv = kv_w + C + hD + dd;
        #pragma unroll 4
        for (int c2 = 0; c2 < 32; c2++) {
            int cc2 = cs*32 + c2;
            part += fbs[cc2] * kvv[(size_t)cc2*(2*C)];
        }
        atomicAdd(&g_at[((size_t)b*T + t)*C + hD + dd], part);
    }

    int o = tid;
    float ecol[D];
    const float* ew = experts_w + ((size_t)t*C + hD)*C + o;
    #pragma unroll
    for (int d2 = 0; d2 < D; d2++) ecol[d2] = ew[(size_t)d2*C];

    float* outb = out + ((size_t)b*ROWS + T)*C;
    int kq = tid / (C/4);
    int o4 = tid % (C/4);
    #pragma unroll 1
    for (int gI = 0; gI < TOPK/4; gI++) {
        #pragma unroll
        for (int j = 0; j < 4; j++) {
            int k = gI*4 + j;
            float s = 0.f;
            #pragma unroll
            for (int d2 = 0; d2 < D; d2++) s += fsh[k][d2] * ecol[d2];
            sc[j][o] = s;
        }
        __syncthreads();
        float4 v = *(const float4*)&sc[kq][4*o4];
        red_add_v4(&outb[(size_t)ish[gI*4 + kq]*C + 4*o4], v);
        __syncthreads();
    }
}

// ---------------- kernel: token_out = at @ experts_w, c-split -----------------
__global__ __launch_bounds__(384) void token_final_kernel(const float* __restrict__ experts_w,
                                                          float* __restrict__ out) {
    int cs = blockIdx.x, t = blockIdx.y;
    int tid = threadIdx.x;
    __shared__ float ats[4][48];
    if (tid < 192) {
        int b = tid / 48, c = tid % 48;
        ats[b][c] = g_at[((size_t)b*T + t)*C + cs*48 + c];
    }
    __syncthreads();
    float a0 = 0.f, a1 = 0.f, a2 = 0.f, a3 = 0.f;
    const float* w = experts_w + (size_t)t*C*C + (size_t)cs*48*C + tid;
    #pragma unroll 4
    for (int c = 0; c < 48; c++) {
        float wv = w[(size_t)c*C];
        a0 += ats[0][c]*wv; a1 += ats[1][c]*wv;
        a2 += ats[2][c]*wv; a3 += ats[3][c]*wv;
    }
    atomicAdd(&out[((size_t)0*ROWS + t)*C + tid], a0);
    atomicAdd(&out[((size_t)1*ROWS + t)*C + tid], a1);
    atomicAdd(&out[((size_t)2*ROWS + t)*C + tid], a2);
    atomicAdd(&out[((size_t)3*ROWS + t)*C + tid], a3);
}

// ---------------- launcher ----------------------------------------------------
extern "C" void kernel_launch(void* const* d_in, const int* in_sizes, int n_in,
                              void* d_out, int out_size) {
    const float* x = nullptr; const float* qs_w = nullptr;
    const float* kv_w = nullptr; const float* experts_w = nullptr;
    for (int i = 0; i < n_in; i++) {
        if (in_sizes[i] == B*ROWS*C)      x = (const float*)d_in[i];
        else if (in_sizes[i] == C*2*C)    kv_w = (const float*)d_in[i];
        else if (in_sizes[i] == T*C*C) {
            if (!qs_w) qs_w = (const float*)d_in[i];
            else       experts_w = (const float*)d_in[i];
        }
    }
    float* out = (float*)d_out;

    cudaFuncSetAttribute(attn_gemm_kernel,
                         cudaFuncAttributeMaxDynamicSharedMemorySize,
                         (int)GEMM_SMEM_BYTES);
    cudaFuncSetAttribute(qk_kernel,
                         cudaFuncAttributeMaxDynamicSharedMemorySize,
                         (int)QK_SMEM_BYTES);

    // launch order keeps the bf16 gemm at captured index 3
    q_kernel<<<dim3(8, T), 384>>>(x, qs_w);                              // 0
    qk_kernel<<<96, 384, QK_SMEM_BYTES>>>(kv_w);                         // 1
    zero_all_kernel<<<1024, 256>>>((float4*)d_out, out_size / 4);        // 2
    attn_gemm_kernel<<<dim3(NF/128, B), 256, GEMM_SMEM_BYTES>>>(x);      // 3
    topk_stage1_kernel<<<B*HT*2, 256>>>();                               // 4
    gather_scatter_kernel<<<dim3(T, H, B), 384>>>(x, kv_w, experts_w, out); // 5
    token_final_kernel<<<dim3(8, T), 384>>>(experts_w, out);             // 6
}

// round 16
// speedup vs baseline: 1.2268x; 1.0016x over previous
#include <cuda_runtime.h>
#include <math.h>
#include <float.h>

#define B 4
#define T 8
#define NF 8192
#define C 384
#define H 12
#define TOPK 32
#define D 32
#define HT (H*T)        /* 96 */
#define ROWS (T+NF)     /* 8200 */
#define NH (NF/2)       /* 4096 per stage-1 half */
#define SCALE 0.17677669529663687f

typedef unsigned long long ull;
typedef unsigned int uint;

// ---------------- scratch (static device globals; no runtime alloc) ----------
__device__ float g_q[B*T*C];
__device__ float g_at[B*T*C];
__device__ float g_qk[B*HT*C];
__device__ float g_attn[(size_t)B*HT*NF];         // ~12.6MB
__device__ ull   g_cand[B*HT][2][TOPK];           // stage-1 sorted candidates

// ---------------- helpers -----------------------------------------------------
__device__ __forceinline__ void red_add_v4(float* p, float4 v) {
    asm volatile("red.global.add.v4.f32 [%0], {%1, %2, %3, %4};"
                 :: "l"(p), "f"(v.x), "f"(v.y), "f"(v.z), "f"(v.w) : "memory");
}
__device__ __forceinline__ void mma_bf16(float* d,
                                         uint a0, uint a1, uint a2, uint a3,
                                         uint b0, uint b1) {
    asm("mma.sync.aligned.m16n8k16.row.col.f32.bf16.bf16.f32 "
        "{%0,%1,%2,%3}, {%4,%5,%6,%7}, {%8,%9}, {%0,%1,%2,%3};"
        : "+f"(d[0]), "+f"(d[1]), "+f"(d[2]), "+f"(d[3])
        : "r"(a0), "r"(a1), "r"(a2), "r"(a3), "r"(b0), "r"(b1));
}
__device__ __forceinline__ uint prmt_hi(uint lo, uint hi) {
    uint r; asm("prmt.b32 %0, %1, %2, 0x7632;" : "=r"(r) : "r"(lo), "r"(hi));
    return r;
}
__device__ __forceinline__ uint cvt_bf16x2(float hi, float lo) {
    uint r; asm("cvt.rn.satfinite.bf16x2.f32 %0, %1, %2;" : "=r"(r) : "f"(hi), "f"(lo));
    return r;
}
__device__ __forceinline__ unsigned enc_key(unsigned b) {
    return (b & 0x80000000u) ? ~b : (b | 0x80000000u);
}
__device__ __forceinline__ float dec_key(unsigned u) {
    unsigned b = (u & 0x80000000u) ? (u ^ 0x80000000u) : ~u;
    return __uint_as_float(b);
}

// ---------------- kernel: zero output + scratch accumulators ------------------
__global__ void zero_all_kernel(float4* __restrict__ out, int n4) {
    int total = n4 + 2*(B*T*C/4);
    float4 z = make_float4(0.f, 0.f, 0.f, 0.f);
    for (int i = blockIdx.x * blockDim.x + threadIdx.x; i < total;
         i += gridDim.x * blockDim.x) {
        if (i < n4) out[i] = z;
        else {
            int j = i - n4;
            if (j < B*T*C/4) ((float4*)g_q)[j] = z;
            else             ((float4*)g_at)[j - B*T*C/4] = z;
        }
    }
}

// ---------------- kernel: q projection, c-split with atomic reduction ---------
__global__ __launch_bounds__(384) void q_kernel(const float* __restrict__ x,
                                                const float* __restrict__ qs_w) {
    int cs = blockIdx.x, t = blockIdx.y;
    int tid = threadIdx.x;
    __shared__ float xs[4][48];
    if (tid < 192) {
        int b = tid / 48, c = tid % 48;
        xs[b][c] = x[((size_t)b*ROWS + t)*C + cs*48 + c];
    }
    __syncthreads();
    float a0 = 0.f, a1 = 0.f, a2 = 0.f, a3 = 0.f;
    const float* w = qs_w + (size_t)t*C*C + (size_t)cs*48*C + tid;
    #pragma unroll 4
    for (int c = 0; c < 48; c++) {
        float wv = w[(size_t)c*C];
        a0 += xs[0][c]*wv; a1 += xs[1][c]*wv;
        a2 += xs[2][c]*wv; a3 += xs[3][c]*wv;
    }
    atomicAdd(&g_q[(0*T + t)*C + tid], a0);
    atomicAdd(&g_q[(1*T + t)*C + tid], a1);
    atomicAdd(&g_q[(2*T + t)*C + tid], a2);
    atomicAdd(&g_q[(3*T + t)*C + tid], a3);
}

// ---------------- kernel: qk fold ---------------------------------------------
#define QPAD 392
#define QK_SMEM_BYTES ((32*QPAD + 4*QPAD)*4)
__global__ __launch_bounds__(384) void qk_kernel(const float* __restrict__ kv_w) {
    extern __shared__ float qsm[];
    float* qs  = qsm;                      // [32][QPAD]
    float* kvs = qsm + 32*QPAD;            // [4][QPAD]

    int c0 = blockIdx.x * 4;
    int tid = threadIdx.x;
    int h = tid >> 5, t = (tid >> 2) & 7, cl = tid & 3;

    #pragma unroll
    for (int r = 0; r < 32; r++) qs[r*QPAD + tid] = g_q[r*C + tid];
    #pragma unroll
    for (int r = 0; r < 4; r++)
        kvs[r*QPAD + tid] = kv_w[(size_t)(c0 + r)*(2*C) + tid];
    __syncthreads();

    const float* krow = &kvs[cl*QPAD + h*D];
    #pragma unroll
    for (int b = 0; b < 4; b++) {
        const float* qrow = &qs[(b*8 + t)*QPAD + h*D];
        float s = 0.f;
        #pragma unroll
        for (int d = 0; d < D; d++) s += qrow[d] * krow[d];
        g_qk[(((size_t)b*H + h)*T + t)*C + c0 + cl] = s * SCALE;
    }
}

// ---------------- kernel: attn GEMM, 3xBF16 split (measured 31.9us) -----------
#define WPR 20
#define AH_OFF 0
#define AL_OFF (96*WPR)
#define BH_OFF (2*96*WPR)
#define BL_OFF (2*96*WPR + 128*WPR)
#define BUFW   (2*96*WPR + 2*128*WPR)     /* 8960 words */
#define GEMM_SMEM_BYTES (2*BUFW*4)        /* 71680 B */

__device__ __forceinline__ void split_store(uint* hi, uint* lo,
                                            int row, int kq, float4 v) {
    uint bx = __float_as_uint(v.x), by = __float_as_uint(v.y);
    uint bz = __float_as_uint(v.z), bw = __float_as_uint(v.w);
    float lx = v.x - __uint_as_float(bx & 0xFFFF0000u);
    float ly = v.y - __uint_as_float(by & 0xFFFF0000u);
    float lz = v.z - __uint_as_float(bz & 0xFFFF0000u);
    float lw = v.w - __uint_as_float(bw & 0xFFFF0000u);
    uint h0 = prmt_hi(bx, by);
    uint h1 = prmt_hi(bz, bw);
    uint l0 = cvt_bf16x2(ly, lx);
    uint l1 = cvt_bf16x2(lw, lz);
    *(uint2*)&hi[row*WPR + 2*kq] = make_uint2(h0, h1);
    *(uint2*)&lo[row*WPR + 2*kq] = make_uint2(l0, l1);
}

__global__ __launch_bounds__(256, 2) void attn_gemm_kernel(const float* __restrict__ x) {
    extern __shared__ __align__(16) uint smem_u[];

    int b  = blockIdx.y;
    int n0 = blockIdx.x * 128;
    int tid = threadIdx.x;
    int wid = tid >> 5, lane = tid & 31;
    int g = lane >> 2, tig = lane & 3;
    int wm = wid & 1, wn = wid >> 1;       // 2x4 warp grid

    const float* qk   = g_qk + (size_t)b*HT*C;
    const float* feat = x + ((size_t)b*ROWS + T)*C;

    int ar[3], ak[3], br[4], bk[4];
    #pragma unroll
    for (int j = 0; j < 3; j++) { int idx = tid + j*256; ar[j] = idx >> 3; ak[j] = idx & 7; }
    #pragma unroll
    for (int j = 0; j < 4; j++) { int idx = tid + j*256; br[j] = idx >> 3; bk[j] = idx & 7; }

    float acc[3][4][4];
    #pragma unroll
    for (int i = 0; i < 3; i++)
        #pragma unroll
        for (int j = 0; j < 4; j++)
            #pragma unroll
            for (int r = 0; r < 4; r++) acc[i][j][r] = 0.f;

    float4 pa[3], pb[4];
    #pragma unroll
    for (int j = 0; j < 3; j++) pa[j] = *(const float4*)&qk[(size_t)ar[j]*C + ak[j]*4];
    #pragma unroll
    for (int j = 0; j < 4; j++) pb[j] = *(const float4*)&feat[(size_t)(n0 + br[j])*C + bk[j]*4];
    {
        uint* buf = smem_u;
        #pragma unroll
        for (int j = 0; j < 3; j++)
            split_store(buf + AH_OFF, buf + AL_OFF, ar[j], ak[j], pa[j]);
        #pragma unroll
        for (int j = 0; j < 4; j++)
            split_store(buf + BH_OFF, buf + BL_OFF, br[j], bk[j], pb[j]);
    }
    __syncthreads();

    #pragma unroll 1
    for (int t = 0; t < 12; t++) {
        if (t < 11) {                      // prefetch chunk t+1 into registers
            int c1 = (t + 1) * 32;
            #pragma unroll
            for (int j = 0; j < 3; j++)
                pa[j] = *(const float4*)&qk[(size_t)ar[j]*C + c1 + ak[j]*4];
            #pragma unroll
            for (int j = 0; j < 4; j++)
                pb[j] = *(const float4*)&feat[(size_t)(n0 + br[j])*C + c1 + bk[j]*4];
        }

        const uint* buf = smem_u + (t & 1)*BUFW;
        #pragma unroll
        for (int h16 = 0; h16 < 2; h16++) {
            int wo = h16*8;
            uint bh[4][2], bl[4][2];
            #pragma unroll
            for (int nt = 0; nt < 4; nt++) {
                int n = wn*32 + nt*8 + g;
                bh[nt][0] = buf[BH_OFF + n*WPR + wo + tig];
                bh[nt][1] = buf[BH_OFF + n*WPR + wo + tig + 4];
                bl[nt][0] = buf[BL_OFF + n*WPR + wo + tig];
                bl[nt][1] = buf[BL_OFF + n*WPR + wo + tig + 4];
            }
            #pragma unroll
            for (int mt = 0; mt < 3; mt++) {
                int r0 = (wm*48 + mt*16 + g)*WPR + wo;
                int r1 = r0 + 8*WPR;
                uint ah0 = buf[AH_OFF + r0 + tig];
                uint ah1 = buf[AH_OFF + r1 + tig];
                uint ah2 = buf[AH_OFF + r0 + tig + 4];
                uint ah3 = buf[AH_OFF + r1 + tig + 4];
                uint al0 = buf[AL_OFF + r0 + tig];
                uint al1 = buf[AL_OFF + r1 + tig];
                uint al2 = buf[AL_OFF + r0 + tig + 4];
                uint al3 = buf[AL_OFF + r1 + tig + 4];
                #pragma unroll
                for (int nt = 0; nt < 4; nt++) {
                    float* d = acc[mt][nt];
                    mma_bf16(d, ah0, ah1, ah2, ah3, bh[nt][0], bh[nt][1]);
                    mma_bf16(d, ah0, ah1, ah2, ah3, bl[nt][0], bl[nt][1]);
                    mma_bf16(d, al0, al1, al2, al3, bh[nt][0], bh[nt][1]);
                }
            }
        }

        if (t < 11) {                      // split+store chunk t+1
            uint* dbuf = smem_u + ((t + 1) & 1)*BUFW;
            #pragma unroll
            for (int j = 0; j < 3; j++)
                split_store(dbuf + AH_OFF, dbuf + AL_OFF, ar[j], ak[j], pa[j]);
            #pragma unroll
            for (int j = 0; j < 4; j++)
                split_store(dbuf + BH_OFF, dbuf + BL_OFF, br[j], bk[j], pb[j]);
            __syncthreads();
        }
    }

    float* outp = g_attn + (size_t)b*HT*NF;
    #pragma unroll
    for (int mt = 0; mt < 3; mt++) {
        int m0 = wm*48 + mt*16;
        #pragma unroll
        for (int nt = 0; nt < 4; nt++) {
            int nc = n0 + wn*32 + nt*8 + 2*tig;
            *(float2*)&outp[(size_t)(m0 + g    )*NF + nc] =
                make_float2(acc[mt][nt][0], acc[mt][nt][1]);
            *(float2*)&outp[(size_t)(m0 + g + 8)*NF + nc] =
                make_float2(acc[mt][nt][2], acc[mt][nt][3]);
        }
    }
}

// ---------------- top-k stage 1 (measured R13 scalar version) -----------------
__global__ __launch_bounds__(256) void topk_stage1_kernel() {
    int blk  = blockIdx.x;
    int row  = blk >> 1;
    int half = blk & 1;
    int base = half * NH;
    int tid = threadIdx.x;
    int lane = tid & 31, wp = tid >> 5;
    __shared__ unsigned keys[NH];
    __shared__ unsigned hist[256];
    __shared__ unsigned wsuf[8];
    __shared__ unsigned sh_need, sh_prefix;
    __shared__ int cntG;
    __shared__ unsigned candK[TOPK];
    __shared__ int candI[TOPK];
    __shared__ int ri[256];

    hist[tid] = 0;
    if (tid == 0) { sh_need = TOPK; sh_prefix = 0; cntG = 0; }
    __syncthreads();

    const uint4* src = (const uint4*)(g_attn + (size_t)row*NF + base);
    for (int i = tid; i < NH/4; i += 256) {
        uint4 u = src[i];
        unsigned k0 = enc_key(u.x), k1 = enc_key(u.y);
        unsigned k2 = enc_key(u.z), k3 = enc_key(u.w);
        keys[4*i+0] = k0; keys[4*i+1] = k1;
        keys[4*i+2] = k2; keys[4*i+3] = k3;
        atomicAdd(&hist[k0 >> 24], 1u);
        atomicAdd(&hist[k1 >> 24], 1u);
        atomicAdd(&hist[k2 >> 24], 1u);
        atomicAdd(&hist[k3 >> 24], 1u);
    }
    __syncthreads();

    #pragma unroll
    for (int pass = 0; pass < 4; pass++) {
        int shift = 24 - 8*pass;
        if (pass > 0) {
            hist[tid] = 0;
            __syncthreads();
            unsigned pref  = sh_prefix;
            unsigned pmask = 0xFFFFFFFFu << (shift + 8);
            for (int i = tid; i < NH; i += 256) {
                unsigned k = keys[i];
                if ((k & pmask) == pref) atomicAdd(&hist[(k >> shift) & 255], 1u);
            }
            __syncthreads();
        }

        unsigned v = hist[tid];
        unsigned inc = v;
        #pragma unroll
        for (int s = 1; s < 32; s <<= 1) {
            unsigned tv = __shfl_down_sync(0xffffffffu, inc, s);
            if (lane + s < 32) inc += tv;
        }
        if (lane == 0) wsuf[wp] = inc;
        __syncthreads();
        if (tid < 8) {
            unsigned tv = wsuf[tid];
            #pragma unroll
            for (int s = 1; s < 8; s <<= 1) {
                unsigned t2 = __shfl_down_sync(0xffu, tv, s);
                if (tid + s < 8) tv += t2;
            }
            wsuf[tid] = tv;
        }
        __syncthreads();
        unsigned incl = inc + (wp < 7 ? wsuf[wp + 1] : 0u);
        unsigned need = sh_need;
        unsigned excl = incl - v;
        if (incl >= need && excl < need) {
            sh_prefix = sh_prefix | ((unsigned)tid << shift);
            sh_need   = need - excl;
        }
        __syncthreads();
    }
    unsigned V = sh_prefix;
    int E = (int)sh_need;

    for (int i = tid; i < NH; i += 256) {
        unsigned k = keys[i];
        if (k > V) { int p = atomicAdd(&cntG, 1); candK[p] = k; candI[p] = base + i; }
    }
    __syncthreads();
    int G = cntG;

    int last = -1;
    for (int e = 0; e < E; e++) {
        int best = NH;
        for (int i = tid; i < NH; i += 256)
            if (keys[i] == V && i > last && i < best) best = i;
        ri[tid] = best;
        __syncthreads();
        for (int s = 128; s > 0; s >>= 1) {
            if (tid < s) ri[tid] = min(ri[tid], ri[tid + s]);
            __syncthreads();
        }
        int widx = ri[0];
        if (tid == 0) { candK[G + e] = V; candI[G + e] = base + widx; }
        last = widx;
        __syncthreads();
    }

    if (tid < 32) {
        unsigned k = candK[tid];
        int ix = candI[tid];
        ull ck = ((ull)k << 32) | (ull)(0xFFFFFFFFu - (unsigned)ix);
        int rank = 0;
        #pragma unroll
        for (int j = 0; j < 32; j++) {
            ull o = __shfl_sync(0xffffffffu, ck, j);
            rank += (o > ck);
        }
        g_cand[row][half][rank] = ck;
    }
}

// ---------------- kernel: merge + softmax + gather + at-proj + scatter --------
__global__ __launch_bounds__(384) void gather_scatter_kernel(const float* __restrict__ x,
                                                             const float* __restrict__ kv_w,
                                                             const float* __restrict__ experts_w,
                                                             float* __restrict__ out) {
    int t = blockIdx.x, h = blockIdx.y, b = blockIdx.z;
    int tid = threadIdx.x;                 // 384
    __shared__ float wsh[TOPK];
    __shared__ int   ish[TOPK];
    __shared__ float fsh[TOPK][D];
    __shared__ float fbs[C];
    __shared__ __align__(16) float sc[4][C];

    int row = (b*H + h)*T + t;
    if (tid < 32) {
        ull a = g_cand[row][0][tid];
        ull bq = g_cand[row][1][31 - tid];
        ull cc = a > bq ? a : bq;
        #pragma unroll
        for (int st = 16; st > 0; st >>= 1) {
            ull o = __shfl_xor_sync(0xffffffffu, cc, st);
            bool up = (tid & st) == 0;
            cc = up ? (cc > o ? cc : o) : (cc < o ? cc : o);
        }
        float val = dec_key((unsigned)(cc >> 32));
        int   idx = (int)(0xFFFFFFFFu - (unsigned)(cc & 0xFFFFFFFFu));
        float m = __shfl_sync(0xffffffffu, val, 0);
        float e = expf(val - m);
        float sum = e;
        #pragma unroll
        for (int o = 16; o > 0; o >>= 1) sum += __shfl_xor_sync(0xffffffffu, sum, o);
        wsh[tid] = e / sum;
        ish[tid] = idx;
    }
    __syncthreads();

    const float* feat = x + ((size_t)b*ROWS + T)*C;
    int c = tid;
    int hD = h*D;
    bool mine = (c >= hD) && (c < hD + D);
    int d = c - hD;
    float a = 0.f;
    #pragma unroll
    for (int k = 0; k < TOPK; k++) {
        float v  = feat[(size_t)ish[k]*C + c];
        float wv = wsh[k] * v;
        a += wv;
        if (mine) fsh[k][d] = wv;
    }
    fbs[c] = a;
    __syncthreads();

    {
        int dd = tid & 31, cs = tid >> 5;
        float part = 0.f;
        const float* kvv = kv_w + C + hD + dd;
        #pragma unroll 4
        for (int c2 = 0; c2 < 32; c2++) {
            int cc2 = cs*32 + c2;
            part += fbs[cc2] * kvv[(size_t)cc2*(2*C)];
        }
        atomicAdd(&g_at[((size_t)b*T + t)*C + hD + dd], part);
    }

    int o = tid;
    float ecol[D];
    const float* ew = experts_w + ((size_t)t*C + hD)*C + o;
    #pragma unroll
    for (int d2 = 0; d2 < D; d2++) ecol[d2] = ew[(size_t)d2*C];

    float* outb = out + ((size_t)b*ROWS + T)*C;
    int kq = tid / (C/4);
    int o4 = tid % (C/4);
    #pragma unroll 1
    for (int gI = 0; gI < TOPK/4; gI++) {
        #pragma unroll
        for (int j = 0; j < 4; j++) {
            int k = gI*4 + j;
            float s = 0.f;
            #pragma unroll
            for (int d2 = 0; d2 < D; d2++) s += fsh[k][d2] * ecol[d2];
            sc[j][o] = s;
        }
        __syncthreads();
        float4 v = *(const float4*)&sc[kq][4*o4];
        red_add_v4(&outb[(size_t)ish[gI*4 + kq]*C + 4*o4], v);
        __syncthreads();
    }
}

// ---------------- kernel: token_out = at @ experts_w, c-split -----------------
__global__ __launch_bounds__(384) void token_final_kernel(const float* __restrict__ experts_w,
                                                          float* __restrict__ out) {
    int cs = blockIdx.x, t = blockIdx.y;
    int tid = threadIdx.x;
    __shared__ float ats[4][48];
    if (tid < 192) {
        int b = tid / 48, c = tid % 48;
        ats[b][c] = g_at[((size_t)b*T + t)*C + cs*48 + c];
    }
    __syncthreads();
    float a0 = 0.f, a1 = 0.f, a2 = 0.f, a3 = 0.f;
    const float* w = experts_w + (size_t)t*C*C + (size_t)cs*48*C + tid;
    #pragma unroll 4
    for (int c = 0; c < 48; c++) {
        float wv = w[(size_t)c*C];
        a0 += ats[0][c]*wv; a1 += ats[1][c]*wv;
        a2 += ats[2][c]*wv; a3 += ats[3][c]*wv;
    }
    atomicAdd(&out[((size_t)0*ROWS + t)*C + tid], a0);
    atomicAdd(&out[((size_t)1*ROWS + t)*C + tid], a1);
    atomicAdd(&out[((size_t)2*ROWS + t)*C + tid], a2);
    atomicAdd(&out[((size_t)3*ROWS + t)*C + tid], a3);
}

// ---------------- launcher ----------------------------------------------------
extern "C" void kernel_launch(void* const* d_in, const int* in_sizes, int n_in,
                              void* d_out, int out_size) {
    const float* x = nullptr; const float* qs_w = nullptr;
    const float* kv_w = nullptr; const float* experts_w = nullptr;
    for (int i = 0; i < n_in; i++) {
        if (in_sizes[i] == B*ROWS*C)      x = (const float*)d_in[i];
        else if (in_sizes[i] == C*2*C)    kv_w = (const float*)d_in[i];
        else if (in_sizes[i] == T*C*C) {
            if (!qs_w) qs_w = (const float*)d_in[i];
            else       experts_w = (const float*)d_in[i];
        }
    }
    float* out = (float*)d_out;

    cudaFuncSetAttribute(attn_gemm_kernel,
                         cudaFuncAttributeMaxDynamicSharedMemorySize,
                         (int)GEMM_SMEM_BYTES);
    cudaFuncSetAttribute(qk_kernel,
                         cudaFuncAttributeMaxDynamicSharedMemorySize,
                         (int)QK_SMEM_BYTES);

    // R13 launch order (measured 100.4us): gemm at captured index 3
    q_kernel<<<dim3(8, T), 384>>>(x, qs_w);                              // 0
    qk_kernel<<<96, 384, QK_SMEM_BYTES>>>(kv_w);                         // 1
    zero_all_kernel<<<1024, 256>>>((float4*)d_out, out_size / 4);        // 2
    attn_gemm_kernel<<<dim3(NF/128, B), 256, GEMM_SMEM_BYTES>>>(x);      // 3
    topk_stage1_kernel<<<B*HT*2, 256>>>();                               // 4
    gather_scatter_kernel<<<dim3(T, H, B), 384>>>(x, kv_w, experts_w, out); // 5
    token_final_kernel<<<dim3(8, T), 384>>>(experts_w, out);             // 6
}